// round 6
// baseline (speedup 1.0000x reference)
#include <cuda_runtime.h>
#include <cuda_fp8.h>
#include <stdint.h>

#define SEQ 80
#define EMB 100
#define VOCAB 10000
#define BMAX 16384

// Precomputed emb @ Wx0 + b0, columns stored permuted: unit j -> slot sidx(j)
__device__ float g_embW0[VOCAB * 64];
// Transposed tokens [SEQ][B]
__device__ int g_tokT[SEQ * BMAX];
// Weight B-fragments, fp8: word = (m*8+nt)*128 + lane*4 + (u*2+c)
__device__ uint32_t g_wfrag[3 * 8 * 32 * 4];

#define EMBW_BLOCKS 313
#define WFRAG_BLOCKS 3

// unit held at k-position kp (verified R4/R5)
__host__ __device__ __forceinline__ int punit(int kp) {
    return (kp & 0x30) | ((kp & 2) << 2) | ((kp & 0xC) >> 1) | (kp & 1);
}
// storage slot of unit j in permuted embW0 row
__host__ __device__ __forceinline__ int sidx(int j) {
    int nt = j >> 3, tq = (j >> 1) & 3, e = j & 1;
    return (nt >> 1) * 16 + tq * 4 + (nt & 1) * 2 + e;
}

// ---------------------------------------------------------------------------
// Prep (fused): embW0 build | weight fragment build | token transpose
// ---------------------------------------------------------------------------
__global__ void __launch_bounds__(256) prep_kernel(const float* __restrict__ emb,
                                                   const float* __restrict__ Wx0,
                                                   const float* __restrict__ b0,
                                                   const float* __restrict__ Wh0,
                                                   const float* __restrict__ Wx1,
                                                   const float* __restrict__ Wh1,
                                                   const int*   __restrict__ tokens,
                                                   int B) {
    int tid = threadIdx.x;
    if (blockIdx.x < EMBW_BLOCKS) {
        __shared__ float sW[EMB * 64];
        __shared__ float sE[32 * EMB];
        for (int i = tid; i < EMB * 64; i += 256) sW[i] = Wx0[i];
        int vbase = blockIdx.x * 32;
        for (int i = tid; i < 32 * EMB; i += 256) {
            int r = vbase + i / EMB;
            sE[i] = emb[(r < VOCAB ? r : 0) * EMB + i % EMB];
        }
        __syncthreads();

        int tcol = tid & 15;
        int trow = tid >> 4;
        float a0[4], a1[4];
        *reinterpret_cast<float4*>(a0) = *reinterpret_cast<const float4*>(b0 + tcol * 4);
        *reinterpret_cast<float4*>(a1) = *reinterpret_cast<float4*>(a0);
        const float* e0 = sE + trow * EMB;
        const float* e1 = sE + (trow + 16) * EMB;
        const float4* sW4 = reinterpret_cast<const float4*>(sW);
        #pragma unroll 10
        for (int k = 0; k < EMB; ++k) {
            float4 w = sW4[k * 16 + tcol];
            float ev0 = e0[k], ev1 = e1[k];
            a0[0] += ev0 * w.x; a0[1] += ev0 * w.y; a0[2] += ev0 * w.z; a0[3] += ev0 * w.w;
            a1[0] += ev1 * w.x; a1[1] += ev1 * w.y; a1[2] += ev1 * w.z; a1[3] += ev1 * w.w;
        }
        int v0 = vbase + trow, v1 = vbase + trow + 16;
        #pragma unroll
        for (int jj = 0; jj < 4; ++jj) {
            int s = sidx(tcol * 4 + jj);
            if (v0 < VOCAB) g_embW0[v0 * 64 + s] = a0[jj];
            if (v1 < VOCAB) g_embW0[v1 * 64 + s] = a1[jj];
        }
        return;
    }
    if (blockIdx.x < EMBW_BLOCKS + WFRAG_BLOCKS) {
        int m = blockIdx.x - EMBW_BLOCKS;
        const float* W = (m == 0) ? Wh0 : (m == 1) ? Wx1 : Wh1;
        for (int t = tid; t < 1024; t += 256) {
            int lane = t & 31, r = t >> 5;
            int nt = r >> 2, u = (r >> 1) & 1, c = r & 1;
            int n = nt * 8 + (lane >> 2);
            uint32_t word = 0;
            #pragma unroll
            for (int bB = 0; bB < 4; ++bB) {
                int kp = c * 32 + u * 16 + (lane & 3) * 4 + bB;
                __nv_fp8_e4m3 q(W[punit(kp) * 64 + n]);
                word |= (uint32_t)q.__x << (8 * bB);
            }
            g_wfrag[(m * 8 + nt) * 128 + lane * 4 + (u * 2 + c)] = word;
        }
        return;
    }
    int b = (blockIdx.x - EMBW_BLOCKS - WFRAG_BLOCKS) * 256 + tid;
    if (b < B) {
        #pragma unroll
        for (int s = 0; s < SEQ; ++s)
            g_tokT[s * B + b] = tokens[b * SEQ + s];
    }
}

// ---------------------------------------------------------------------------
// PTX helpers
// ---------------------------------------------------------------------------
__device__ __forceinline__ void mma_fp8(float& d0, float& d1, float& d2, float& d3,
                                        uint32_t a0, uint32_t a1, uint32_t a2, uint32_t a3,
                                        uint32_t b0, uint32_t b1) {
    asm("mma.sync.aligned.m16n8k32.row.col.f32.e4m3.e4m3.f32 "
        "{%0,%1,%2,%3},{%4,%5,%6,%7},{%8,%9},{%0,%1,%2,%3};"
        : "+f"(d0), "+f"(d1), "+f"(d2), "+f"(d3)
        : "r"(a0), "r"(a1), "r"(a2), "r"(a3), "r"(b0), "r"(b1));
}

__device__ __forceinline__ void mma_fp8_c(float& d0, float& d1, float& d2, float& d3,
                                          uint32_t a0, uint32_t a1, uint32_t a2, uint32_t a3,
                                          uint32_t b0, uint32_t b1, float c0, float c1) {
    asm("mma.sync.aligned.m16n8k32.row.col.f32.e4m3.e4m3.f32 "
        "{%0,%1,%2,%3},{%4,%5,%6,%7},{%8,%9},{%10,%11,%10,%11};"
        : "=f"(d0), "=f"(d1), "=f"(d2), "=f"(d3)
        : "r"(a0), "r"(a1), "r"(a2), "r"(a3), "r"(b0), "r"(b1), "f"(c0), "f"(c1));
}

__device__ __forceinline__ uint32_t f16x2_of(float lo, float hi) {
    uint32_t r;
    asm("cvt.rn.f16x2.f32 %0, %1, %2;" : "=r"(r) : "f"(hi), "f"(lo));
    return r;
}

__device__ __forceinline__ uint32_t tanh_f16x2(uint32_t v) {
    uint32_t r;
    asm("tanh.approx.f16x2 %0, %1;" : "=r"(r) : "r"(v));
    return r;
}

__device__ __forceinline__ uint32_t pack_e4m3(uint32_t fa, uint32_t fb) {
    uint32_t r;
    asm("{\n\t"
        ".reg .b16 lo, hi;\n\t"
        "cvt.rn.satfinite.e4m3x2.f16x2 lo, %1;\n\t"
        "cvt.rn.satfinite.e4m3x2.f16x2 hi, %2;\n\t"
        "mov.b32 %0, {lo, hi};\n\t"
        "}" : "=r"(r) : "r"(fa), "r"(fb));
    return r;
}

__device__ __forceinline__ float fast_tanh(float x) {
    float y;
    asm("tanh.approx.f32 %0, %1;" : "=f"(y) : "f"(x));
    return y;
}

// acc[16] (own half pre-act) -> 4 fp8 A-fragment words (this half's kp group)
__device__ __forceinline__ void tanh_half_frags(const float* acc, uint32_t* hw) {
    uint32_t t0[4], t1[4];
    #pragma unroll
    for (int nt = 0; nt < 4; ++nt) {
        t0[nt] = tanh_f16x2(f16x2_of(acc[2 * nt],     acc[2 * nt + 1]));
        t1[nt] = tanh_f16x2(f16x2_of(acc[8 + 2 * nt], acc[8 + 2 * nt + 1]));
    }
    hw[0] = pack_e4m3(t0[0], t0[1]);
    hw[1] = pack_e4m3(t1[0], t1[1]);
    hw[2] = pack_e4m3(t0[2], t0[3]);
    hw[3] = pack_e4m3(t1[2], t1[3]);
}

// ---------------------------------------------------------------------------
// Kernel 2: N-split fp8 recurrence. CTA = 64 threads = one warp PAIR sharing
// 16 batch rows; warp `half` owns output units [32*half, 32*half+32).
// Halves exchanged via one uint4 STS/LDS + __syncthreads per layer.
// grid = B/16 = 1024 CTAs -> ~14 warps/SM.
// ---------------------------------------------------------------------------
__global__ void __launch_bounds__(64, 7) rnn_kernel(
    const float* __restrict__ b1,
    const float* __restrict__ Wout,
    const float* __restrict__ bout,
    float*       __restrict__ out,
    int B) {
    __shared__ __align__(16) uint4 sEx[2][2][32];  // [layer][half][lane]
    __shared__ float sHd[2][16];

    const int lane = threadIdx.x & 31;
    const int half = threadIdx.x >> 5;
    const int g  = lane >> 2;
    const int tq = lane & 3;
    const int base = blockIdx.x * 16;

    int rraw[2], rc[2];
    #pragma unroll
    for (int i = 0; i < 2; ++i) {
        rraw[i] = base + g + 8 * i;
        rc[i]   = rraw[i] < B ? rraw[i] : (B - 1);
    }

    // ---- own-half weight fragments (3 matrices x 4 n-tiles x 4 words) ----
    uint32_t wf[48];
    {
        const uint4* wp = reinterpret_cast<const uint4*>(g_wfrag);
        #pragma unroll
        for (int m = 0; m < 3; ++m) {
            #pragma unroll
            for (int nt = 0; nt < 4; ++nt) {
                uint4 v = wp[(m * 8 + half * 4 + nt) * 32 + lane];
                wf[m * 16 + nt * 4 + 0] = v.x;
                wf[m * 16 + nt * 4 + 1] = v.y;
                wf[m * 16 + nt * 4 + 2] = v.z;
                wf[m * 16 + nt * 4 + 3] = v.w;
            }
        }
    }

    float b1f[8];
    #pragma unroll
    for (int nt = 0; nt < 4; ++nt) {
        b1f[nt * 2]     = b1[half * 32 + nt * 8 + tq * 2];
        b1f[nt * 2 + 1] = b1[half * 32 + nt * 8 + tq * 2 + 1];
    }

    float    accA[16], accB[16];
    uint32_t h0f[8], h1f[8];
    #pragma unroll
    for (int i = 0; i < 8; ++i) { h0f[i] = 0u; h1f[i] = 0u; }

    // step-0 gather (own half: 32 contiguous-permuted slots)
    #pragma unroll
    for (int i = 0; i < 2; ++i) {
        int tok = g_tokT[rc[i]];
        const float* rowp = g_embW0 + tok * 64 + half * 32 + tq * 4;
        float4 v0 = *reinterpret_cast<const float4*>(rowp);
        float4 v1 = *reinterpret_cast<const float4*>(rowp + 16);
        accA[i*8+0]=v0.x; accA[i*8+1]=v0.y; accA[i*8+2]=v0.z; accA[i*8+3]=v0.w;
        accA[i*8+4]=v1.x; accA[i*8+5]=v1.y; accA[i*8+6]=v1.z; accA[i*8+7]=v1.w;
    }

    #pragma unroll 1
    for (int ts = 0; ts < SEQ; ++ts) {
        int tsn = (ts + 1 < SEQ) ? ts + 1 : SEQ - 1;
        int tkn[2];
        #pragma unroll
        for (int i = 0; i < 2; ++i) tkn[i] = g_tokT[tsn * B + rc[i]];

        // interleaved: accA += h0@Wh0 (own nt) ; accB = b1 + h1@Wh1 (own nt)
        #pragma unroll
        for (int nt = 0; nt < 4; ++nt) {
            mma_fp8(accA[nt*2], accA[nt*2+1], accA[8+nt*2], accA[8+nt*2+1],
                    h0f[0], h0f[1], h0f[2], h0f[3],
                    wf[nt*4 + 0], wf[nt*4 + 2]);
            mma_fp8_c(accB[nt*2], accB[nt*2+1], accB[8+nt*2], accB[8+nt*2+1],
                      h1f[0], h1f[1], h1f[2], h1f[3],
                      wf[32 + nt*4 + 0], wf[32 + nt*4 + 2],
                      b1f[2*nt], b1f[2*nt+1]);
        }
        #pragma unroll
        for (int nt = 0; nt < 4; ++nt) {
            mma_fp8(accA[nt*2], accA[nt*2+1], accA[8+nt*2], accA[8+nt*2+1],
                    h0f[4], h0f[5], h0f[6], h0f[7],
                    wf[nt*4 + 1], wf[nt*4 + 3]);
            mma_fp8(accB[nt*2], accB[nt*2+1], accB[8+nt*2], accB[8+nt*2+1],
                    h1f[4], h1f[5], h1f[6], h1f[7],
                    wf[32 + nt*4 + 1], wf[32 + nt*4 + 3]);
        }

        // h0 own half = tanh(accA)
        uint32_t hw[4];
        tanh_half_frags(accA, hw);

        // prefetch next-step gather into accA (now free)
        #pragma unroll
        for (int i = 0; i < 2; ++i) {
            const float* rowp = g_embW0 + tkn[i] * 64 + half * 32 + tq * 4;
            float4 v0 = *reinterpret_cast<const float4*>(rowp);
            float4 v1 = *reinterpret_cast<const float4*>(rowp + 16);
            accA[i*8+0]=v0.x; accA[i*8+1]=v0.y; accA[i*8+2]=v0.z; accA[i*8+3]=v0.w;
            accA[i*8+4]=v1.x; accA[i*8+5]=v1.y; accA[i*8+6]=v1.z; accA[i*8+7]=v1.w;
        }

        // exchange h0 halves
        sEx[0][half][lane] = make_uint4(hw[0], hw[1], hw[2], hw[3]);
        __syncthreads();
        {
            uint4 p = sEx[0][half ^ 1][lane];
            h0f[half*4+0] = hw[0]; h0f[half*4+1] = hw[1];
            h0f[half*4+2] = hw[2]; h0f[half*4+3] = hw[3];
            h0f[(half^1)*4+0] = p.x; h0f[(half^1)*4+1] = p.y;
            h0f[(half^1)*4+2] = p.z; h0f[(half^1)*4+3] = p.w;
        }

        // accB += h0new @ Wx1 (own nt, full K)
        #pragma unroll
        for (int c = 0; c < 2; ++c) {
            #pragma unroll
            for (int nt = 0; nt < 4; ++nt) {
                mma_fp8(accB[nt*2], accB[nt*2+1], accB[8+nt*2], accB[8+nt*2+1],
                        h0f[c*4+0], h0f[c*4+1], h0f[c*4+2], h0f[c*4+3],
                        wf[16 + nt*4 + c], wf[16 + nt*4 + 2 + c]);
            }
        }

        // h1 own half = tanh(accB); exchange
        tanh_half_frags(accB, hw);
        sEx[1][half][lane] = make_uint4(hw[0], hw[1], hw[2], hw[3]);
        __syncthreads();
        {
            uint4 p = sEx[1][half ^ 1][lane];
            h1f[half*4+0] = hw[0]; h1f[half*4+1] = hw[1];
            h1f[half*4+2] = hw[2]; h1f[half*4+3] = hw[3];
            h1f[(half^1)*4+0] = p.x; h1f[(half^1)*4+1] = p.y;
            h1f[(half^1)*4+2] = p.z; h1f[(half^1)*4+3] = p.w;
        }
    }

    // ---- head: sigmoid(tanh(accB) @ Wout + bout), halves combined via smem ----
    float wo[8];
    #pragma unroll
    for (int nt = 0; nt < 4; ++nt) {
        float2 v = *reinterpret_cast<const float2*>(Wout + half * 32 + nt * 8 + tq * 2);
        wo[nt * 2] = v.x; wo[nt * 2 + 1] = v.y;
    }
    float bo = bout[0];
    float sv[2];
    #pragma unroll
    for (int i = 0; i < 2; ++i) {
        float s = 0.f;
        #pragma unroll
        for (int nt = 0; nt < 4; ++nt) {
            s += fast_tanh(accB[i * 8 + nt * 2])     * wo[nt * 2];
            s += fast_tanh(accB[i * 8 + nt * 2 + 1]) * wo[nt * 2 + 1];
        }
        s += __shfl_xor_sync(0xffffffffu, s, 1);
        s += __shfl_xor_sync(0xffffffffu, s, 2);
        sv[i] = s;
        if (tq == 0) sHd[half][i * 8 + g] = s;
    }
    __syncthreads();
    if (half == 0 && tq == 0) {
        #pragma unroll
        for (int i = 0; i < 2; ++i) {
            if (rraw[i] < B) {
                float tot = sv[i] + sHd[1][i * 8 + g] + bo;
                out[rraw[i]] = 1.0f / (1.0f + __expf(-tot));
            }
        }
    }
}

// ---------------------------------------------------------------------------
extern "C" void kernel_launch(void* const* d_in, const int* in_sizes, int n_in,
                              void* d_out, int out_size) {
    const int*   tokens = (const int*)  d_in[0];
    const float* emb    = (const float*)d_in[1];
    const float* Wx0    = (const float*)d_in[2];
    const float* Wh0    = (const float*)d_in[3];
    const float* b0     = (const float*)d_in[4];
    const float* Wx1    = (const float*)d_in[5];
    const float* Wh1    = (const float*)d_in[6];
    const float* b1     = (const float*)d_in[7];
    const float* Wout   = (const float*)d_in[8];
    const float* bout   = (const float*)d_in[9];
    float* out = (float*)d_out;

    int B = in_sizes[0] / SEQ;
    if (B > BMAX) B = BMAX;

    int prep_blocks = EMBW_BLOCKS + WFRAG_BLOCKS + (B + 255) / 256;
    prep_kernel<<<prep_blocks, 256>>>(emb, Wx0, b0, Wh0, Wx1, Wh1, tokens, B);

    int nblocks = (B + 15) / 16;
    rnn_kernel<<<nblocks, 64>>>(b1, Wout, bout, out, B);
}